// round 1
// baseline (speedup 1.0000x reference)
#include <cuda_runtime.h>

// ---------------------------------------------------------------------------
// PerceiverAttention: b=8, n=4096, l=64, D=1024, heads=16, dh=64
// Pipeline:
//   1. detect mask dtype (bool/int32/float32) -> g_maskfmt
//   2. build additive bias (0 / -1e30) over (b, n+l)
//   3. LayerNorm x and latents -> XN (33280 x 1024), and ln_lat (512 x 1024)
//   4. q   = ln_lat @ Wq        (512 x 1024 x 1024)
//   5. kv  = XN @ Wkv           (33280 x 2048 x 1024)   <-- dominant GEMM
//   6. flash attention per (b,h): O = softmax(q k^T/8 + bias) v
//   7. out = O @ Wout           (512 x 1024 x 1024)
// ---------------------------------------------------------------------------

#define B_      8
#define NSEQ    4096
#define LATN    64
#define DMODEL  1024
#define HEADS   16
#define DH      64
#define NTOT    (NSEQ + LATN)      // 4160
#define MROWS   (B_ * NTOT)        // 33280

// Scratch (device globals: allocation-free per harness rules)
__device__ float g_xn[(size_t)MROWS * DMODEL];          // 136 MB
__device__ float g_lnlat[(size_t)B_ * LATN * DMODEL];   // 2 MB
__device__ float g_kv[(size_t)MROWS * 2 * DMODEL];      // 272 MB
__device__ float g_q[(size_t)B_ * LATN * DMODEL];       // 2 MB
__device__ float g_atto[(size_t)B_ * LATN * DMODEL];    // 2 MB
__device__ float g_bias[B_ * NTOT];
__device__ int   g_maskfmt;                             // 0=u8 bool, 1=int32, 2=float32

// ---------------------------------------------------------------------------
// Mask dtype fingerprint. Reads first 256 words (1 KB, always within buffer:
// the smallest candidate layout is 32768 bytes).
//   int32:  every word in {0,1}
//   float32: every word in {0, 0x3F800000}
//   else: numpy bool (1 byte/elem)
// For a random half-ones bool mask, the misclassification probability is ~0.
// ---------------------------------------------------------------------------
__global__ void detect_mask_kernel(const void* __restrict__ mask) {
    const unsigned int* w = (const unsigned int*)mask;
    bool isInt = true, isFloat = true;
    for (int i = 0; i < 256; i++) {
        unsigned int v = w[i];
        if (v > 1u) isInt = false;
        if (v != 0u && v != 0x3F800000u) isFloat = false;
    }
    g_maskfmt = isInt ? 1 : (isFloat ? 2 : 0);
}

__global__ void build_bias_kernel(const void* __restrict__ mask) {
    int idx = blockIdx.x * blockDim.x + threadIdx.x;
    if (idx >= B_ * NTOT) return;
    int b = idx / NTOT;
    int j = idx - b * NTOT;
    float v = 0.f;
    if (j < NSEQ) {
        int fmt = g_maskfmt;
        long off = (long)b * NSEQ + j;
        int mv;
        if (fmt == 1)      mv = ((const int*)mask)[off] != 0;
        else if (fmt == 2) mv = ((const float*)mask)[off] != 0.f;
        else               mv = ((const unsigned char*)mask)[off] != 0;
        v = mv ? 0.f : -1e30f;
    }
    g_bias[idx] = v;
}

// ---------------------------------------------------------------------------
// LayerNorm: one block per row of the concatenated [x ; latents] matrix.
// 256 threads, float4 per thread (D=1024). Writes XN; latent rows also go to
// the contiguous ln_lat buffer used by the q projection.
// ---------------------------------------------------------------------------
__global__ void ln_kernel(const float* __restrict__ x, const float* __restrict__ lat,
                          const float* __restrict__ g1, const float* __restrict__ b1,
                          const float* __restrict__ g2, const float* __restrict__ b2) {
    const int r = blockIdx.x;
    const int b = r / NTOT;
    const int pos = r - b * NTOT;
    const bool isLat = pos >= NSEQ;
    const float* src;
    const float* g;
    const float* bb;
    if (!isLat) { src = x  + ((size_t)b * NSEQ + pos) * DMODEL;         g = g1; bb = b1; }
    else        { src = lat + ((size_t)b * LATN + (pos - NSEQ)) * DMODEL; g = g2; bb = b2; }

    const int tid = threadIdx.x;  // 256
    float4 v = reinterpret_cast<const float4*>(src)[tid];
    float s  = v.x + v.y + v.z + v.w;
    float sq = v.x*v.x + v.y*v.y + v.z*v.z + v.w*v.w;
    #pragma unroll
    for (int off = 16; off > 0; off >>= 1) {
        s  += __shfl_xor_sync(0xffffffffu, s,  off);
        sq += __shfl_xor_sync(0xffffffffu, sq, off);
    }
    __shared__ float sh[2][8];
    __shared__ float tot[2];
    if ((tid & 31) == 0) { sh[0][tid >> 5] = s; sh[1][tid >> 5] = sq; }
    __syncthreads();
    if (tid == 0) {
        float a = 0.f, c = 0.f;
        #pragma unroll
        for (int i = 0; i < 8; i++) { a += sh[0][i]; c += sh[1][i]; }
        tot[0] = a; tot[1] = c;
    }
    __syncthreads();
    const float mean = tot[0] * (1.f / DMODEL);
    const float var  = tot[1] * (1.f / DMODEL) - mean * mean;
    const float inv  = rsqrtf(var + 1e-5f);

    float4 gv = reinterpret_cast<const float4*>(g)[tid];
    float4 bv = reinterpret_cast<const float4*>(bb)[tid];
    float4 o;
    o.x = (v.x - mean) * inv * gv.x + bv.x;
    o.y = (v.y - mean) * inv * gv.y + bv.y;
    o.z = (v.z - mean) * inv * gv.z + bv.z;
    o.w = (v.w - mean) * inv * gv.w + bv.w;
    reinterpret_cast<float4*>(&g_xn[(size_t)r * DMODEL])[tid] = o;
    if (isLat)
        reinterpret_cast<float4*>(&g_lnlat[((size_t)b * LATN + (pos - NSEQ)) * DMODEL])[tid] = o;
}

// ---------------------------------------------------------------------------
// Classic register-blocked SGEMM: C(MxN) = A(MxK,row) * B(KxN,row).
// All problem dims here are exact multiples of the tiles -> no edge guards.
// ---------------------------------------------------------------------------
template<int BM, int BN, int BK, int TM, int TN>
__global__ void sgemm_kernel(const float* __restrict__ A, const float* __restrict__ B,
                             float* __restrict__ C, int M, int N, int K) {
    constexpr int THREADS = (BM / TM) * (BN / TN);
    __shared__ float As[BK][BM];   // transposed A tile
    __shared__ float Bs[BK][BN];
    const int tid = threadIdx.x;
    const int bn = blockIdx.x * BN;
    const int bm = blockIdx.y * BM;
    const int tx = tid % (BN / TN);
    const int ty = tid / (BN / TN);
    const int arow = ty * TM;
    const int bcol = tx * TN;
    float acc[TM][TN] = {};

    for (int k0 = 0; k0 < K; k0 += BK) {
        #pragma unroll
        for (int idx = tid; idx < BM * BK / 4; idx += THREADS) {
            int row = idx / (BK / 4);
            int c4  = (idx % (BK / 4)) * 4;
            const float4 v = *reinterpret_cast<const float4*>(
                &A[(size_t)(bm + row) * K + k0 + c4]);
            As[c4 + 0][row] = v.x;
            As[c4 + 1][row] = v.y;
            As[c4 + 2][row] = v.z;
            As[c4 + 3][row] = v.w;
        }
        #pragma unroll
        for (int idx = tid; idx < BK * BN / 4; idx += THREADS) {
            int row = idx / (BN / 4);
            int c4  = (idx % (BN / 4)) * 4;
            *reinterpret_cast<float4*>(&Bs[row][c4]) =
                *reinterpret_cast<const float4*>(&B[(size_t)(k0 + row) * N + bn + c4]);
        }
        __syncthreads();
        #pragma unroll
        for (int kk = 0; kk < BK; kk++) {
            float ar[TM], br[TN];
            #pragma unroll
            for (int i = 0; i < TM; i++) ar[i] = As[kk][arow + i];
            #pragma unroll
            for (int j = 0; j < TN; j++) br[j] = Bs[kk][bcol + j];
            #pragma unroll
            for (int i = 0; i < TM; i++)
                #pragma unroll
                for (int j = 0; j < TN; j++)
                    acc[i][j] = fmaf(ar[i], br[j], acc[i][j]);
        }
        __syncthreads();
    }
    #pragma unroll
    for (int i = 0; i < TM; i++) {
        float* crow = &C[(size_t)(bm + arow + i) * N + bn + bcol];
        #pragma unroll
        for (int j = 0; j < TN; j += 4) {
            float4 v = make_float4(acc[i][j], acc[i][j+1], acc[i][j+2], acc[i][j+3]);
            *reinterpret_cast<float4*>(&crow[j]) = v;
        }
    }
}

// ---------------------------------------------------------------------------
// Flash attention. One block per (b,h). 256 threads: ty=tid/8 owns query rows
// {ty, ty+32}; tx=tid%8 owns score cols j=tx*4..+4 (chunk=32 keys) and output
// dims d=tx*8..+8. Online softmax with chunk rescale (self-correcting for
// masked-only prefixes). Scale 1/8 = (dh^-0.25)^2 folded into Q.
// ---------------------------------------------------------------------------
#define CH 32
__global__ void attn_kernel(const float* __restrict__ Q, const float* __restrict__ KV,
                            const float* __restrict__ bias, float* __restrict__ O) {
    __shared__ float Qs[LATN][DH + 1];
    __shared__ float Ks[CH][DH + 1];
    __shared__ float Vs[CH][DH + 1];
    __shared__ float Ps[LATN][CH + 1];
    __shared__ float bsm[CH];

    const int bh = blockIdx.x;
    const int b = bh >> 4;
    const int h = bh & 15;
    const int tid = threadIdx.x;
    const int ty = tid >> 3;  // 0..31
    const int tx = tid & 7;   // 0..7

    const float* qbase = Q + (size_t)b * LATN * DMODEL + h * DH;
    for (int idx = tid; idx < LATN * DH; idx += 256) {
        int i = idx >> 6, d = idx & 63;
        Qs[i][d] = qbase[(size_t)i * DMODEL + d] * 0.125f;
    }
    const float* kvb = KV + (size_t)b * NTOT * (2 * DMODEL) + h * DH;
    const float* bb  = bias + b * NTOT;

    float m0 = -3.0e38f, m1 = -3.0e38f, l0 = 0.f, l1 = 0.f;
    float o0[8] = {}, o1[8] = {};

    for (int c = 0; c < NTOT / CH; c++) {
        const int j0 = c * CH;
        __syncthreads();   // retire previous iter's Ks/Vs/Ps readers
        for (int idx = tid; idx < CH * DH; idx += 256) {
            int j = idx >> 6, d = idx & 63;
            const float* p = kvb + (size_t)(j0 + j) * (2 * DMODEL) + d;
            Ks[j][d] = p[0];
            Vs[j][d] = p[DMODEL];
        }
        if (tid < CH) bsm[tid] = bb[j0 + tid];
        __syncthreads();

        float s0[4], s1[4];
        #pragma unroll
        for (int jj = 0; jj < 4; jj++) {
            float bv = bsm[tx * 4 + jj];
            s0[jj] = bv; s1[jj] = bv;
        }
        #pragma unroll 8
        for (int d = 0; d < DH; d++) {
            float q0 = Qs[ty][d], q1 = Qs[ty + 32][d];
            #pragma unroll
            for (int jj = 0; jj < 4; jj++) {
                float kk = Ks[tx * 4 + jj][d];
                s0[jj] = fmaf(q0, kk, s0[jj]);
                s1[jj] = fmaf(q1, kk, s1[jj]);
            }
        }
        float cm0 = s0[0], cm1 = s1[0];
        #pragma unroll
        for (int jj = 1; jj < 4; jj++) { cm0 = fmaxf(cm0, s0[jj]); cm1 = fmaxf(cm1, s1[jj]); }
        #pragma unroll
        for (int off = 1; off < 8; off <<= 1) {
            cm0 = fmaxf(cm0, __shfl_xor_sync(0xffffffffu, cm0, off));
            cm1 = fmaxf(cm1, __shfl_xor_sync(0xffffffffu, cm1, off));
        }
        const float mn0 = fmaxf(m0, cm0), mn1 = fmaxf(m1, cm1);
        float p0[4], p1[4], ls0 = 0.f, ls1 = 0.f;
        #pragma unroll
        for (int jj = 0; jj < 4; jj++) {
            p0[jj] = __expf(s0[jj] - mn0); ls0 += p0[jj];
            p1[jj] = __expf(s1[jj] - mn1); ls1 += p1[jj];
        }
        #pragma unroll
        for (int off = 1; off < 8; off <<= 1) {
            ls0 += __shfl_xor_sync(0xffffffffu, ls0, off);
            ls1 += __shfl_xor_sync(0xffffffffu, ls1, off);
        }
        const float sc0 = __expf(m0 - mn0), sc1 = __expf(m1 - mn1);
        l0 = l0 * sc0 + ls0;
        l1 = l1 * sc1 + ls1;
        #pragma unroll
        for (int dd = 0; dd < 8; dd++) { o0[dd] *= sc0; o1[dd] *= sc1; }
        m0 = mn0; m1 = mn1;
        #pragma unroll
        for (int jj = 0; jj < 4; jj++) {
            Ps[ty][tx * 4 + jj]      = p0[jj];
            Ps[ty + 32][tx * 4 + jj] = p1[jj];
        }
        __syncthreads();
        #pragma unroll 8
        for (int j = 0; j < CH; j++) {
            float pa = Ps[ty][j], pb = Ps[ty + 32][j];
            #pragma unroll
            for (int dd = 0; dd < 8; dd++) {
                float v = Vs[j][tx * 8 + dd];
                o0[dd] = fmaf(pa, v, o0[dd]);
                o1[dd] = fmaf(pb, v, o1[dd]);
            }
        }
    }
    const float inv0 = 1.f / l0, inv1 = 1.f / l1;
    float* obase = O + (size_t)b * LATN * DMODEL + h * DH;
    #pragma unroll
    for (int dd = 0; dd < 8; dd++) {
        obase[(size_t)ty * DMODEL + tx * 8 + dd]        = o0[dd] * inv0;
        obase[(size_t)(ty + 32) * DMODEL + tx * 8 + dd] = o1[dd] * inv1;
    }
}

// ---------------------------------------------------------------------------
extern "C" void kernel_launch(void* const* d_in, const int* in_sizes, int n_in,
                              void* d_out, int out_size) {
    const float* x    = (const float*)d_in[0];
    const float* lat  = (const float*)d_in[1];
    const void*  mask = d_in[2];
    const float* g1   = (const float*)d_in[3];
    const float* b1   = (const float*)d_in[4];
    const float* g2   = (const float*)d_in[5];
    const float* b2   = (const float*)d_in[6];
    const float* Wq   = (const float*)d_in[7];
    const float* Wkv  = (const float*)d_in[8];
    const float* Wout = (const float*)d_in[9];
    float* out = (float*)d_out;

    float *xn, *lnlat, *kv, *q, *atto, *bias;
    cudaGetSymbolAddress((void**)&xn,    g_xn);
    cudaGetSymbolAddress((void**)&lnlat, g_lnlat);
    cudaGetSymbolAddress((void**)&kv,    g_kv);
    cudaGetSymbolAddress((void**)&q,     g_q);
    cudaGetSymbolAddress((void**)&atto,  g_atto);
    cudaGetSymbolAddress((void**)&bias,  g_bias);

    detect_mask_kernel<<<1, 1>>>(mask);
    build_bias_kernel<<<(B_ * NTOT + 255) / 256, 256>>>(mask);
    ln_kernel<<<MROWS, 256>>>(x, lat, g1, b1, g2, b2);

    // q = ln_lat @ Wq : 512 x 1024 x 1024 (small-tile config for parallelism)
    sgemm_kernel<64, 64, 16, 4, 4>
        <<<dim3(DMODEL / 64, (B_ * LATN) / 64), 256>>>(lnlat, Wq, q, B_ * LATN, DMODEL, DMODEL);

    // kv = XN @ Wkv : 33280 x 2048 x 1024 (dominant GEMM)
    sgemm_kernel<128, 128, 16, 8, 8>
        <<<dim3((2 * DMODEL) / 128, MROWS / 128), 256>>>(xn, Wkv, kv, MROWS, 2 * DMODEL, DMODEL);

    // attention per (b, h)
    attn_kernel<<<B_ * HEADS, 256>>>(q, kv, bias, atto);

    // out = attO @ Wout : 512 x 1024 x 1024
    sgemm_kernel<64, 64, 16, 4, 4>
        <<<dim3(DMODEL / 64, (B_ * LATN) / 64), 256>>>(atto, Wout, out, B_ * LATN, DMODEL, DMODEL);
}

// round 3
// speedup vs baseline: 1.9917x; 1.9917x over previous
#include <cuda_runtime.h>
#include <cuda_bf16.h>
#include <cstdint>

// ---------------------------------------------------------------------------
// PerceiverAttention: b=8, n=4096, l=64, D=1024, heads=16, dh=64
//   ln -> bf16 hi/lo split of XN; Wkv -> transposed bf16 hi/lo
//   kv = XN @ Wkv via mma.sync bf16 3-product split GEMM (fp32 accum)
//   (tcgen05 rejected: harness PTX stage targets compute_103 w/o 'a' features)
// ---------------------------------------------------------------------------

#define B_      8
#define NSEQ    4096
#define LATN    64
#define DMODEL  1024
#define HEADS   16
#define DH      64
#define NTOT    (NSEQ + LATN)      // 4160
#define MROWS   (B_ * NTOT)        // 33280
#define NKV     (2 * DMODEL)       // 2048

__device__ __nv_bfloat16 g_ah[(size_t)MROWS * DMODEL];
__device__ __nv_bfloat16 g_al[(size_t)MROWS * DMODEL];
__device__ __nv_bfloat16 g_bh[(size_t)NKV * DMODEL];
__device__ __nv_bfloat16 g_bl[(size_t)NKV * DMODEL];
__device__ float g_lnlat[(size_t)B_ * LATN * DMODEL];
__device__ float g_kv[(size_t)MROWS * NKV];
__device__ float g_q[(size_t)B_ * LATN * DMODEL];
__device__ float g_atto[(size_t)B_ * LATN * DMODEL];
__device__ float g_bias[B_ * NTOT];
__device__ int   g_maskfmt;

// ---------------------------------------------------------------------------
__device__ __forceinline__ uint32_t smem_u32(const void* p) {
    uint32_t a;
    asm("{ .reg .u64 t; cvta.to.shared.u64 t, %1; cvt.u32.u64 %0, t; }" : "=r"(a) : "l"(p));
    return a;
}
__device__ __forceinline__ void cpasync16(uint32_t dst, const void* src) {
    asm volatile("cp.async.cg.shared.global [%0], [%1], 16;" :: "r"(dst), "l"(src) : "memory");
}
__device__ __forceinline__ void cp_commit() { asm volatile("cp.async.commit_group;" ::: "memory"); }
__device__ __forceinline__ void cp_wait1()  { asm volatile("cp.async.wait_group 1;" ::: "memory"); }
__device__ __forceinline__ void cp_wait0()  { asm volatile("cp.async.wait_group 0;" ::: "memory"); }

__device__ __forceinline__ void ldm4(uint32_t r[4], uint32_t addr) {
    asm volatile("ldmatrix.sync.aligned.m8n8.x4.shared.b16 {%0,%1,%2,%3}, [%4];"
                 : "=r"(r[0]), "=r"(r[1]), "=r"(r[2]), "=r"(r[3]) : "r"(addr));
}
__device__ __forceinline__ void mma16816(float d[4], const uint32_t a[4], const uint32_t b[2]) {
    asm volatile("mma.sync.aligned.m16n8k16.row.col.f32.bf16.bf16.f32 "
                 "{%0,%1,%2,%3}, {%4,%5,%6,%7}, {%8,%9}, {%0,%1,%2,%3};"
                 : "+f"(d[0]), "+f"(d[1]), "+f"(d[2]), "+f"(d[3])
                 : "r"(a[0]), "r"(a[1]), "r"(a[2]), "r"(a[3]), "r"(b[0]), "r"(b[1]));
}

// ---------------------------------------------------------------------------
// Mask dtype fingerprint + additive bias
// ---------------------------------------------------------------------------
__global__ void detect_mask_kernel(const void* __restrict__ mask) {
    const unsigned int* w = (const unsigned int*)mask;
    bool isInt = true, isFloat = true;
    for (int i = 0; i < 256; i++) {
        unsigned int v = w[i];
        if (v > 1u) isInt = false;
        if (v != 0u && v != 0x3F800000u) isFloat = false;
    }
    g_maskfmt = isInt ? 1 : (isFloat ? 2 : 0);
}
__global__ void build_bias_kernel(const void* __restrict__ mask) {
    int idx = blockIdx.x * blockDim.x + threadIdx.x;
    if (idx >= B_ * NTOT) return;
    int b = idx / NTOT;
    int j = idx - b * NTOT;
    float v = 0.f;
    if (j < NSEQ) {
        int fmt = g_maskfmt;
        long off = (long)b * NSEQ + j;
        int mv;
        if (fmt == 1)      mv = ((const int*)mask)[off] != 0;
        else if (fmt == 2) mv = ((const float*)mask)[off] != 0.f;
        else               mv = ((const unsigned char*)mask)[off] != 0;
        v = mv ? 0.f : -1e30f;
    }
    g_bias[idx] = v;
}

// ---------------------------------------------------------------------------
// LayerNorm -> bf16 hi/lo split + fp32 ln_lat
// ---------------------------------------------------------------------------
__device__ __forceinline__ void split2(float a, float b, __nv_bfloat162* ph, __nv_bfloat162* pl) {
    __nv_bfloat16 ha = __float2bfloat16_rn(a), hb = __float2bfloat16_rn(b);
    __nv_bfloat162 h, l;
    h.x = ha; h.y = hb;
    l.x = __float2bfloat16_rn(a - __bfloat162float(ha));
    l.y = __float2bfloat16_rn(b - __bfloat162float(hb));
    *ph = h; *pl = l;
}

__global__ void ln_kernel(const float* __restrict__ x, const float* __restrict__ lat,
                          const float* __restrict__ g1, const float* __restrict__ b1,
                          const float* __restrict__ g2, const float* __restrict__ b2) {
    const int r = blockIdx.x;
    const int b = r / NTOT;
    const int pos = r - b * NTOT;
    const bool isLat = pos >= NSEQ;
    const float* src;
    const float* g;
    const float* bb;
    if (!isLat) { src = x   + ((size_t)b * NSEQ + pos) * DMODEL;          g = g1; bb = b1; }
    else        { src = lat + ((size_t)b * LATN + (pos - NSEQ)) * DMODEL; g = g2; bb = b2; }

    const int tid = threadIdx.x;  // 256
    float4 v = reinterpret_cast<const float4*>(src)[tid];
    float s  = v.x + v.y + v.z + v.w;
    float sq = v.x*v.x + v.y*v.y + v.z*v.z + v.w*v.w;
    #pragma unroll
    for (int off = 16; off > 0; off >>= 1) {
        s  += __shfl_xor_sync(0xffffffffu, s,  off);
        sq += __shfl_xor_sync(0xffffffffu, sq, off);
    }
    __shared__ float sh[2][8];
    __shared__ float tot[2];
    if ((tid & 31) == 0) { sh[0][tid >> 5] = s; sh[1][tid >> 5] = sq; }
    __syncthreads();
    if (tid == 0) {
        float a = 0.f, c = 0.f;
        #pragma unroll
        for (int i = 0; i < 8; i++) { a += sh[0][i]; c += sh[1][i]; }
        tot[0] = a; tot[1] = c;
    }
    __syncthreads();
    const float mean = tot[0] * (1.f / DMODEL);
    const float var  = tot[1] * (1.f / DMODEL) - mean * mean;
    const float inv  = rsqrtf(var + 1e-5f);

    float4 gv = reinterpret_cast<const float4*>(g)[tid];
    float4 bv = reinterpret_cast<const float4*>(bb)[tid];
    float4 o;
    o.x = (v.x - mean) * inv * gv.x + bv.x;
    o.y = (v.y - mean) * inv * gv.y + bv.y;
    o.z = (v.z - mean) * inv * gv.z + bv.z;
    o.w = (v.w - mean) * inv * gv.w + bv.w;

    __nv_bfloat162 h0, l0, h1, l1;
    split2(o.x, o.y, &h0, &l0);
    split2(o.z, o.w, &h1, &l1);
    __nv_bfloat162* ph = reinterpret_cast<__nv_bfloat162*>(&g_ah[(size_t)r * DMODEL + tid * 4]);
    __nv_bfloat162* pl = reinterpret_cast<__nv_bfloat162*>(&g_al[(size_t)r * DMODEL + tid * 4]);
    ph[0] = h0; ph[1] = h1;
    pl[0] = l0; pl[1] = l1;

    if (isLat)
        reinterpret_cast<float4*>(&g_lnlat[((size_t)b * LATN + (pos - NSEQ)) * DMODEL])[tid] = o;
}

// ---------------------------------------------------------------------------
// Wkv [K=1024][N=2048] fp32 -> transposed bf16 hi/lo [N][K]
// ---------------------------------------------------------------------------
__global__ void convert_w_kernel(const float* __restrict__ W) {
    __shared__ float t[32][33];
    const int n0 = blockIdx.x * 32, k0 = blockIdx.y * 32;
    const int tx = threadIdx.x, ty = threadIdx.y;  // 32 x 8
    #pragma unroll
    for (int r = 0; r < 4; r++)
        t[ty + 8 * r][tx] = W[(size_t)(k0 + ty + 8 * r) * NKV + n0 + tx];
    __syncthreads();
    #pragma unroll
    for (int r = 0; r < 4; r++) {
        int n = n0 + ty + 8 * r;
        int k = k0 + tx;
        float v = t[tx][ty + 8 * r];
        __nv_bfloat16 h = __float2bfloat16_rn(v);
        g_bh[(size_t)n * DMODEL + k] = h;
        g_bl[(size_t)n * DMODEL + k] = __float2bfloat16_rn(v - __bfloat162float(h));
    }
}

// ---------------------------------------------------------------------------
// kv = A @ B^T via mma.sync bf16 (split hi/lo, 3 products, fp32 accum)
// Block 128x128, KC=32, 8 warps (2x4 -> warp tile 64x32), cp.async 2-stage.
// ---------------------------------------------------------------------------
#define BM      128
#define BN      128
#define KC2     32
#define CHUNKS2 (DMODEL / KC2)     // 32
#define RS      80                 // smem row stride bytes (32 bf16 + 16B pad)
#define TILE_B  (128 * RS)         // 10240
#define OFF_AH  0
#define OFF_AL  (1 * TILE_B)
#define OFF_BH  (2 * TILE_B)
#define OFF_BL  (3 * TILE_B)
#define STAGE   (4 * TILE_B)       // 40960
#define KV_SMEM (2 * STAGE)        // 81920

__device__ __forceinline__ void load_stage_kv(
    const __nv_bfloat16* __restrict__ ah, const __nv_bfloat16* __restrict__ al,
    const __nv_bfloat16* __restrict__ bh, const __nv_bfloat16* __restrict__ bl,
    int bm, int bn, int chunk, uint32_t sbuf, int tid)
{
    const int k0 = chunk * KC2;
    #pragma unroll
    for (int i = 0; i < 2; i++) {
        int idx = i * 256 + tid;          // 0..511
        int row = idx >> 2, j = idx & 3;
        uint32_t d = sbuf + (uint32_t)(row * RS + j * 16);
        size_t ga = (size_t)(bm + row) * DMODEL + k0 + j * 8;
        size_t gb = (size_t)(bn + row) * DMODEL + k0 + j * 8;
        cpasync16(d + OFF_AH, ah + ga);
        cpasync16(d + OFF_AL, al + ga);
        cpasync16(d + OFF_BH, bh + gb);
        cpasync16(d + OFF_BL, bl + gb);
    }
}

__global__ void __launch_bounds__(256)
kv_mma_kernel(const __nv_bfloat16* __restrict__ ah, const __nv_bfloat16* __restrict__ al,
              const __nv_bfloat16* __restrict__ bh, const __nv_bfloat16* __restrict__ bl,
              float* __restrict__ C)
{
    extern __shared__ __align__(16) char dsm[];
    const uint32_t sb = smem_u32(dsm);
    const int tid = threadIdx.x;
    const int lane = tid & 31, wid = tid >> 5;
    const int wm = wid >> 2, wn = wid & 3;          // 2 x 4 warp grid
    const int bm = blockIdx.y * BM, bn = blockIdx.x * BN;

    float acc[4][4][4] = {};   // [mf][nf][reg]

    // lane-derived ldmatrix source offsets
    const int mat = lane >> 3, r8 = lane & 7;
    const int aRow = (mat & 1) * 8 + r8;            // A: mat0 m0-7 k0-7, mat1 m8-15 k0-7, mat2 m0-7 k8-15, mat3 m8-15 k8-15
    const int aColB = (mat >> 1) * 16;
    const int bRow = (mat >> 1) * 8 + r8;           // B: mat0 n0-7 k0-7, mat1 n0-7 k8-15, mat2 n8-15 k0-7, mat3 n8-15 k8-15
    const int bColB = (mat & 1) * 16;

    load_stage_kv(ah, al, bh, bl, bm, bn, 0, sb, tid);
    cp_commit();
    load_stage_kv(ah, al, bh, bl, bm, bn, 1, sb + STAGE, tid);
    cp_commit();

    for (int c = 0; c < CHUNKS2; c++) {
        if (c == CHUNKS2 - 1) cp_wait0(); else cp_wait1();
        __syncthreads();
        const uint32_t buf = sb + (uint32_t)((c & 1) * STAGE);

        #pragma unroll
        for (int ks = 0; ks < 2; ks++) {
            uint32_t ahf[4][4], alf[4][4], bhf[4][2], blf[4][2];
            #pragma unroll
            for (int mf = 0; mf < 4; mf++) {
                uint32_t ra = buf + (uint32_t)((wm * 64 + mf * 16 + aRow) * RS + ks * 32 + aColB);
                ldm4(ahf[mf], ra + OFF_AH);
                ldm4(alf[mf], ra + OFF_AL);
            }
            #pragma unroll
            for (int nfp = 0; nfp < 2; nfp++) {
                uint32_t rb = buf + (uint32_t)((wn * 32 + nfp * 16 + bRow) * RS + ks * 32 + bColB);
                uint32_t t[4];
                ldm4(t, rb + OFF_BH);
                bhf[2*nfp][0] = t[0]; bhf[2*nfp][1] = t[1];
                bhf[2*nfp+1][0] = t[2]; bhf[2*nfp+1][1] = t[3];
                ldm4(t, rb + OFF_BL);
                blf[2*nfp][0] = t[0]; blf[2*nfp][1] = t[1];
                blf[2*nfp+1][0] = t[2]; blf[2*nfp+1][1] = t[3];
            }
            #pragma unroll
            for (int mf = 0; mf < 4; mf++)
                #pragma unroll
                for (int nf = 0; nf < 4; nf++) {
                    mma16816(acc[mf][nf], ahf[mf], bhf[nf]);
                    mma16816(acc[mf][nf], ahf[mf], blf[nf]);
                    mma16816(acc[mf][nf], alf[mf], bhf[nf]);
                }
        }
        __syncthreads();
        if (c + 2 < CHUNKS2) {
            load_stage_kv(ah, al, bh, bl, bm, bn, c + 2, sb + (uint32_t)((c & 1) * STAGE), tid);
            cp_commit();
        }
    }

    // epilogue: fp32 acc -> C
    const int tr = lane >> 2, tc = (lane & 3) * 2;
    const int r0 = bm + wm * 64, c0 = bn + wn * 32;
    #pragma unroll
    for (int mf = 0; mf < 4; mf++)
        #pragma unroll
        for (int nf = 0; nf < 4; nf++) {
            int row = r0 + mf * 16 + tr;
            int col = c0 + nf * 8 + tc;
            *reinterpret_cast<float2*>(&C[(size_t)row * NKV + col]) =
                make_float2(acc[mf][nf][0], acc[mf][nf][1]);
            *reinterpret_cast<float2*>(&C[(size_t)(row + 8) * NKV + col]) =
                make_float2(acc[mf][nf][2], acc[mf][nf][3]);
        }
}

// ---------------------------------------------------------------------------
// fp32 SGEMM for the two small projections
// ---------------------------------------------------------------------------
template<int TBM, int TBN, int TBK, int TM, int TN>
__global__ void sgemm_kernel(const float* __restrict__ A, const float* __restrict__ B,
                             float* __restrict__ C, int M, int N, int K) {
    constexpr int THREADS = (TBM / TM) * (TBN / TN);
    __shared__ float As[TBK][TBM];
    __shared__ float Bs[TBK][TBN];
    const int tid = threadIdx.x;
    const int bn = blockIdx.x * TBN;
    const int bm = blockIdx.y * TBM;
    const int tx = tid % (TBN / TN);
    const int ty = tid / (TBN / TN);
    const int arow = ty * TM;
    const int bcol = tx * TN;
    float acc[TM][TN] = {};

    for (int k0 = 0; k0 < K; k0 += TBK) {
        #pragma unroll
        for (int idx = tid; idx < TBM * TBK / 4; idx += THREADS) {
            int row = idx / (TBK / 4);
            int c4  = (idx % (TBK / 4)) * 4;
            const float4 v = *reinterpret_cast<const float4*>(
                &A[(size_t)(bm + row) * K + k0 + c4]);
            As[c4 + 0][row] = v.x;
            As[c4 + 1][row] = v.y;
            As[c4 + 2][row] = v.z;
            As[c4 + 3][row] = v.w;
        }
        #pragma unroll
        for (int idx = tid; idx < TBK * TBN / 4; idx += THREADS) {
            int row = idx / (TBN / 4);
            int c4  = (idx % (TBN / 4)) * 4;
            *reinterpret_cast<float4*>(&Bs[row][c4]) =
                *reinterpret_cast<const float4*>(&B[(size_t)(k0 + row) * N + bn + c4]);
        }
        __syncthreads();
        #pragma unroll
        for (int kk = 0; kk < TBK; kk++) {
            float ar[TM], br[TN];
            #pragma unroll
            for (int i = 0; i < TM; i++) ar[i] = As[kk][arow + i];
            #pragma unroll
            for (int j = 0; j < TN; j++) br[j] = Bs[kk][bcol + j];
            #pragma unroll
            for (int i = 0; i < TM; i++)
                #pragma unroll
                for (int j = 0; j < TN; j++)
                    acc[i][j] = fmaf(ar[i], br[j], acc[i][j]);
        }
        __syncthreads();
    }
    #pragma unroll
    for (int i = 0; i < TM; i++) {
        float* crow = &C[(size_t)(bm + arow + i) * N + bn + bcol];
        #pragma unroll
        for (int j = 0; j < TN; j += 4) {
            float4 v = make_float4(acc[i][j], acc[i][j+1], acc[i][j+2], acc[i][j+3]);
            *reinterpret_cast<float4*>(&crow[j]) = v;
        }
    }
}

// ---------------------------------------------------------------------------
// Flash attention (fp32)
// ---------------------------------------------------------------------------
#define CH 32
__global__ void attn_kernel(const float* __restrict__ Q, const float* __restrict__ KV,
                            const float* __restrict__ bias, float* __restrict__ O) {
    __shared__ float Qs[LATN][DH + 1];
    __shared__ float Ks[CH][DH + 1];
    __shared__ float Vs[CH][DH + 1];
    __shared__ float Ps[LATN][CH + 1];
    __shared__ float bsm[CH];

    const int bh = blockIdx.x;
    const int b = bh >> 4;
    const int h = bh & 15;
    const int tid = threadIdx.x;
    const int ty = tid >> 3;
    const int tx = tid & 7;

    const float* qbase = Q + (size_t)b * LATN * DMODEL + h * DH;
    for (int idx = tid; idx < LATN * DH; idx += 256) {
        int i = idx >> 6, d = idx & 63;
        Qs[i][d] = qbase[(size_t)i * DMODEL + d] * 0.125f;
    }
    const float* kvb = KV + (size_t)b * NTOT * NKV + h * DH;
    const float* bb  = bias + b * NTOT;

    float m0 = -3.0e38f, m1 = -3.0e38f, l0 = 0.f, l1 = 0.f;
    float o0[8] = {}, o1[8] = {};

    for (int c = 0; c < NTOT / CH; c++) {
        const int j0 = c * CH;
        __syncthreads();
        for (int idx = tid; idx < CH * DH; idx += 256) {
            int j = idx >> 6, d = idx & 63;
            const float* p = kvb + (size_t)(j0 + j) * NKV + d;
            Ks[j][d] = p[0];
            Vs[j][d] = p[DMODEL];
        }
        if (tid < CH) bsm[tid] = bb[j0 + tid];
        __syncthreads();

        float s0[4], s1[4];
        #pragma unroll
        for (int jj = 0; jj < 4; jj++) {
            float bv = bsm[tx * 4 + jj];
            s0[jj] = bv; s1[jj] = bv;
        }
        #pragma unroll 8
        for (int d = 0; d < DH; d++) {
            float q0 = Qs[ty][d], q1 = Qs[ty + 32][d];
            #pragma unroll
            for (int jj = 0; jj < 4; jj++) {
                float kk = Ks[tx * 4 + jj][d];
                s0[jj] = fmaf(q0, kk, s0[jj]);
                s1[jj] = fmaf(q1, kk, s1[jj]);
            }
        }
        float cm0 = s0[0], cm1 = s1[0];
        #pragma unroll
        for (int jj = 1; jj < 4; jj++) { cm0 = fmaxf(cm0, s0[jj]); cm1 = fmaxf(cm1, s1[jj]); }
        #pragma unroll
        for (int off = 1; off < 8; off <<= 1) {
            cm0 = fmaxf(cm0, __shfl_xor_sync(0xffffffffu, cm0, off));
            cm1 = fmaxf(cm1, __shfl_xor_sync(0xffffffffu, cm1, off));
        }
        const float mn0 = fmaxf(m0, cm0), mn1 = fmaxf(m1, cm1);
        float p0[4], p1[4], ls0 = 0.f, ls1 = 0.f;
        #pragma unroll
        for (int jj = 0; jj < 4; jj++) {
            p0[jj] = __expf(s0[jj] - mn0); ls0 += p0[jj];
            p1[jj] = __expf(s1[jj] - mn1); ls1 += p1[jj];
        }
        #pragma unroll
        for (int off = 1; off < 8; off <<= 1) {
            ls0 += __shfl_xor_sync(0xffffffffu, ls0, off);
            ls1 += __shfl_xor_sync(0xffffffffu, ls1, off);
        }
        const float sc0 = __expf(m0 - mn0), sc1 = __expf(m1 - mn1);
        l0 = l0 * sc0 + ls0;
        l1 = l1 * sc1 + ls1;
        #pragma unroll
        for (int dd = 0; dd < 8; dd++) { o0[dd] *= sc0; o1[dd] *= sc1; }
        m0 = mn0; m1 = mn1;
        #pragma unroll
        for (int jj = 0; jj < 4; jj++) {
            Ps[ty][tx * 4 + jj]      = p0[jj];
            Ps[ty + 32][tx * 4 + jj] = p1[jj];
        }
        __syncthreads();
        #pragma unroll 8
        for (int j = 0; j < CH; j++) {
            float pa = Ps[ty][j], pb = Ps[ty + 32][j];
            #pragma unroll
            for (int dd = 0; dd < 8; dd++) {
                float v = Vs[j][tx * 8 + dd];
                o0[dd] = fmaf(pa, v, o0[dd]);
                o1[dd] = fmaf(pb, v, o1[dd]);
            }
        }
    }
    const float inv0 = 1.f / l0, inv1 = 1.f / l1;
    float* obase = O + (size_t)b * LATN * DMODEL + h * DH;
    #pragma unroll
    for (int dd = 0; dd < 8; dd++) {
        obase[(size_t)ty * DMODEL + tx * 8 + dd]        = o0[dd] * inv0;
        obase[(size_t)(ty + 32) * DMODEL + tx * 8 + dd] = o1[dd] * inv1;
    }
}

// ---------------------------------------------------------------------------
extern "C" void kernel_launch(void* const* d_in, const int* in_sizes, int n_in,
                              void* d_out, int out_size) {
    const float* x    = (const float*)d_in[0];
    const float* lat  = (const float*)d_in[1];
    const void*  mask = d_in[2];
    const float* g1   = (const float*)d_in[3];
    const float* b1   = (const float*)d_in[4];
    const float* g2   = (const float*)d_in[5];
    const float* b2   = (const float*)d_in[6];
    const float* Wq   = (const float*)d_in[7];
    const float* Wkv  = (const float*)d_in[8];
    const float* Wout = (const float*)d_in[9];
    float* out = (float*)d_out;

    __nv_bfloat16 *ah, *al, *bh, *bl;
    float *lnlat, *kv, *q, *atto, *bias;
    cudaGetSymbolAddress((void**)&ah,    g_ah);
    cudaGetSymbolAddress((void**)&al,    g_al);
    cudaGetSymbolAddress((void**)&bh,    g_bh);
    cudaGetSymbolAddress((void**)&bl,    g_bl);
    cudaGetSymbolAddress((void**)&lnlat, g_lnlat);
    cudaGetSymbolAddress((void**)&kv,    g_kv);
    cudaGetSymbolAddress((void**)&q,     g_q);
    cudaGetSymbolAddress((void**)&atto,  g_atto);
    cudaGetSymbolAddress((void**)&bias,  g_bias);

    static bool attr_done = false;
    if (!attr_done) {
        cudaFuncSetAttribute(kv_mma_kernel,
                             cudaFuncAttributeMaxDynamicSharedMemorySize, KV_SMEM);
        attr_done = true;
    }

    detect_mask_kernel<<<1, 1>>>(mask);
    build_bias_kernel<<<(B_ * NTOT + 255) / 256, 256>>>(mask);
    ln_kernel<<<MROWS, 256>>>(x, lat, g1, b1, g2, b2);
    convert_w_kernel<<<dim3(NKV / 32, DMODEL / 32), dim3(32, 8)>>>(Wkv);

    // q = ln_lat @ Wq : 512 x 1024 x 1024
    sgemm_kernel<64, 64, 16, 4, 4>
        <<<dim3(DMODEL / 64, (B_ * LATN) / 64), 256>>>(lnlat, Wq, q, B_ * LATN, DMODEL, DMODEL);

    // kv = XN @ Wkv : mma.sync split-bf16, tiles 128x128
    kv_mma_kernel<<<dim3(NKV / BN, MROWS / BM), 256, KV_SMEM>>>(ah, al, bh, bl, kv);

    // attention per (b, h)
    attn_kernel<<<B_ * HEADS, 256>>>(q, kv, bias, atto);

    // out = attO @ Wout : 512 x 1024 x 1024
    sgemm_kernel<64, 64, 16, 4, 4>
        <<<dim3(DMODEL / 64, (B_ * LATN) / 64), 256>>>(atto, Wout, out, B_ * LATN, DMODEL, DMODEL);
}